// round 5
// baseline (speedup 1.0000x reference)
#include <cuda_runtime.h>
#include <math.h>
#include <stdint.h>

#define BSZ   16
#define SEQ   4096
#define NST   256
#define HIN   128
#define HOUT  128
#define MTOT  (BSZ*SEQ)      // 65536
#define CHUNK 64
#define NCH   (SEQ/CHUNK)    // 64

// ------------------------------ scratch -----------------------------------
// g_bu: fp32 interleaved (re,im) Bu values, consumed by the scan (fp32 needed
// for recurrence precision). g_pre16_*: packed bf16x2 hi/lo planes of the
// SHIFTED states pre_t = x_{t-1}, written by scan_phase3, consumed by GEMM2.
// g_u16_* / g_w*_16_*: pre-split bf16x2 planes of u and the weights.
__device__ float2   g_bu[(size_t)MTOT*NST];
__device__ float2   g_part[BSZ*NCH*NST];
__device__ uint32_t g_pre16_hi[(size_t)MTOT*256];
__device__ uint32_t g_pre16_lo[(size_t)MTOT*256];
__device__ uint32_t g_u16_hi[(size_t)MTOT*64];
__device__ uint32_t g_u16_lo[(size_t)MTOT*64];
__device__ uint32_t g_wbu16_hi[512*64];
__device__ uint32_t g_wbu16_lo[512*64];
__device__ uint32_t g_wy16_hi[HOUT*320];
__device__ uint32_t g_wy16_lo[HOUT*320];

// pack two fp32 -> bf16x2 (v0 in lower half)
__device__ __forceinline__ uint32_t packbf(float v0, float v1) {
    uint32_t r;
    asm("cvt.rn.bf16x2.f32 %0, %1, %2;" : "=r"(r) : "f"(v1), "f"(v0));
    return r;
}
// split (v0,v1) into hi/lo bf16x2 words
__device__ __forceinline__ void split2(float v0, float v1,
                                       uint32_t& hi, uint32_t& lo) {
    hi = packbf(v0, v1);
    float h0 = __uint_as_float(hi << 16);
    float h1 = __uint_as_float(hi & 0xffff0000u);
    lo = packbf(v0 - h0, v1 - h1);
}

#define MMA_BF16(d, a, b0, b1)                                        \
    asm("mma.sync.aligned.m16n8k16.row.col.f32.bf16.bf16.f32 "        \
        "{%0,%1,%2,%3},{%4,%5,%6,%7},{%8,%9},{%0,%1,%2,%3};"          \
        : "+f"(d[0]), "+f"(d[1]), "+f"(d[2]), "+f"(d[3])              \
        : "r"(a[0]), "r"(a[1]), "r"(a[2]), "r"(a[3]), "r"(b0), "r"(b1))

#define CP16(dst, src)                                                \
    asm volatile("cp.async.cg.shared.global [%0], [%1], 16;"          \
                 :: "r"(dst), "l"(src))
#define CP_COMMIT() asm volatile("cp.async.commit_group;" ::: "memory")

// smem: 2 buffers x 4 planes (Ahi,Alo,Whi,Wlo) x 128 rows x 36 words
// (row stride 144B: 16B-aligned, conflict-free fragment loads).
#define RSTR   36
#define PLW    (128*RSTR)       // 4608 words per plane
#define BUFW   (4*PLW)          // 18432
#define SMEM_BYTES (2*BUFW*4)   // 147456

// ---------------------------------------------------------------------------
// prep_w: split weight planes.
//   wbu rows n=2*state+parity: (parity?Bim:Bre)[state][k]*gamma[state], K=128
//   wy  rows o, word j: j<256 -> (Cre[o][j], -Cim[o][j]); else D pair.
// ---------------------------------------------------------------------------
__global__ __launch_bounds__(256) void prep_w(
    const float* __restrict__ Bre, const float* __restrict__ Bim,
    const float* __restrict__ gamma_log,
    const float* __restrict__ Cre, const float* __restrict__ Cim,
    const float* __restrict__ Dm)
{
    int i = blockIdx.x * 256 + threadIdx.x;
    if (i < 512 * 64) {
        int n = i >> 6, j = i & 63;
        const float* B = (n & 1) ? Bim : Bre;
        float g = expf(gamma_log[n >> 1]);
        float v0 = B[(n >> 1) * HIN + 2 * j] * g;
        float v1 = B[(n >> 1) * HIN + 2 * j + 1] * g;
        uint32_t hi, lo; split2(v0, v1, hi, lo);
        g_wbu16_hi[i] = hi; g_wbu16_lo[i] = lo;
    } else if (i < 512 * 64 + HOUT * 320) {
        int t = i - 512 * 64;
        int o = t / 320, j = t % 320;
        float v0, v1;
        if (j < 256) { v0 = Cre[o * NST + j]; v1 = -Cim[o * NST + j]; }
        else { v0 = Dm[o * HIN + 2 * (j - 256)]; v1 = Dm[o * HIN + 2 * (j - 256) + 1]; }
        uint32_t hi, lo; split2(v0, v1, hi, lo);
        g_wy16_hi[t] = hi; g_wy16_lo[t] = lo;
    }
}

// prep_u: split u into bf16x2 hi/lo planes [m][64 words].
__global__ __launch_bounds__(256) void prep_u(const float* __restrict__ u)
{
    size_t i = (size_t)blockIdx.x * 256 + threadIdx.x;   // word index
    float2 v = ((const float2*)u)[i];
    uint32_t hi, lo; split2(v.x, v.y, hi, lo);
    g_u16_hi[i] = hi; g_u16_lo[i] = lo;
}

// ---------------------------------------------------------------------------
// Tensor-core GEMM (pre-split operands, cp.async pipeline):
//   C[128m, 128n] = A[128, K] x W[128n, K]^T  via 3-product bf16 split.
// MODE 0: A = u16 (K=128, 2 chunks); W = wbu16 tile ntile; out -> g_bu fp32.
// MODE 1: A = [pre16 (512) | u16 (128)] (K=640, 10 chunks); W = wy16; out -> y.
// ---------------------------------------------------------------------------
template<int MODE>
__global__ __launch_bounds__(256, 1) void mma_gemm(float* __restrict__ y)
{
    extern __shared__ uint32_t sm[];
    uint32_t smb;
    asm("{ .reg .u64 t; cvta.to.shared.u64 t, %1; cvt.u32.u64 %0, t; }"
        : "=r"(smb) : "l"(sm));
    const int tid = threadIdx.x, lane = tid & 31, wid = tid >> 5;
    const int warp_m = (wid & 3) * 32, warp_n = (wid >> 2) * 64;
    const int ntile = (MODE == 0) ? blockIdx.x : 0;
    const int m0 = blockIdx.y * 128;
    const int NC = (MODE == 0) ? 2 : 10;

    float acc[2][8][4];
    #pragma unroll
    for (int f = 0; f < 2; f++)
        #pragma unroll
        for (int j = 0; j < 8; j++)
            #pragma unroll
            for (int q = 0; q < 4; q++) acc[f][j][q] = 0.f;

    // cp.async copy of chunk c into buffer buf: thread t<128 -> A row t,
    // t>=128 -> W row t-128; 8x16B per plane (hi+lo).
    auto cpy = [&](int c, int buf) {
        const uint32_t dbase = smb + (uint32_t)buf * BUFW * 4;
        if (tid < 128) {
            const int r = tid;
            const uint32_t *shi, *slo;
            if (MODE == 0) {
                size_t o = (size_t)(m0 + r) * 64 + c * 32;
                shi = g_u16_hi + o; slo = g_u16_lo + o;
            } else if (c < 8) {
                size_t o = (size_t)(m0 + r) * 256 + c * 32;
                shi = g_pre16_hi + o; slo = g_pre16_lo + o;
            } else {
                size_t o = (size_t)(m0 + r) * 64 + (c - 8) * 32;
                shi = g_u16_hi + o; slo = g_u16_lo + o;
            }
            uint32_t d0 = dbase + (r * RSTR) * 4;
            uint32_t d1 = dbase + (PLW + r * RSTR) * 4;
            #pragma unroll
            for (int i = 0; i < 8; i++) {
                CP16(d0 + i * 16, shi + i * 4);
                CP16(d1 + i * 16, slo + i * 4);
            }
        } else {
            const int r = tid - 128;
            const uint32_t *shi, *slo;
            if (MODE == 0) {
                size_t o = (size_t)(ntile * 128 + r) * 64 + c * 32;
                shi = g_wbu16_hi + o; slo = g_wbu16_lo + o;
            } else {
                size_t o = (size_t)r * 320 + c * 32;
                shi = g_wy16_hi + o; slo = g_wy16_lo + o;
            }
            uint32_t d0 = dbase + (2 * PLW + r * RSTR) * 4;
            uint32_t d1 = dbase + (3 * PLW + r * RSTR) * 4;
            #pragma unroll
            for (int i = 0; i < 8; i++) {
                CP16(d0 + i * 16, shi + i * 4);
                CP16(d1 + i * 16, slo + i * 4);
            }
        }
    };

    auto comp = [&](int buf) {
        const uint32_t* base = sm + buf * BUFW;
        const int r0 = lane >> 2, kp = lane & 3;
        #pragma unroll
        for (int ks = 0; ks < 4; ks++) {
            const int kw = ks * 8 + kp;
            uint32_t ah[2][4], al[2][4];
            #pragma unroll
            for (int f = 0; f < 2; f++) {
                const uint32_t* pa = base + (warp_m + f * 16 + r0) * RSTR + kw;
                ah[f][0] = pa[0];   ah[f][2] = pa[4];
                ah[f][1] = pa[288]; ah[f][3] = pa[292];     // +8 rows
                const uint32_t* pl = pa + PLW;
                al[f][0] = pl[0];   al[f][2] = pl[4];
                al[f][1] = pl[288]; al[f][3] = pl[292];
            }
            #pragma unroll
            for (int j = 0; j < 8; j++) {
                const uint32_t* pw = base + 2 * PLW + (warp_n + j * 8 + r0) * RSTR + kw;
                uint32_t bh0 = pw[0],   bh1 = pw[4];
                uint32_t bl0 = pw[PLW], bl1 = pw[PLW + 4];
                #pragma unroll
                for (int f = 0; f < 2; f++) {
                    MMA_BF16(acc[f][j], ah[f], bh0, bh1);
                    MMA_BF16(acc[f][j], ah[f], bl0, bl1);
                    MMA_BF16(acc[f][j], al[f], bh0, bh1);
                }
            }
        }
    };

    cpy(0, 0); CP_COMMIT();
    cpy(1, 1); CP_COMMIT();
    #pragma unroll 1
    for (int c = 0; c < NC; c++) {
        if (c + 1 < NC) asm volatile("cp.async.wait_group 1;" ::: "memory");
        else            asm volatile("cp.async.wait_group 0;" ::: "memory");
        __syncthreads();
        comp(c & 1);
        __syncthreads();
        if (c + 2 < NC) { cpy(c + 2, c & 1); CP_COMMIT(); }
    }

    float* dst;
    int stride;
    if (MODE == 0) { dst = (float*)g_bu + (size_t)ntile * 128; stride = 512; }
    else           { dst = y;                                   stride = HOUT; }
    #pragma unroll
    for (int f = 0; f < 2; f++) {
        const int m = m0 + warp_m + f * 16 + (lane >> 2);
        #pragma unroll
        for (int j = 0; j < 8; j++) {
            const int n = warp_n + j * 8 + (lane & 3) * 2;
            *(float2*)(dst + (size_t)m * stride + n) =
                make_float2(acc[f][j][0], acc[f][j][1]);
            *(float2*)(dst + (size_t)(m + 8) * stride + n) =
                make_float2(acc[f][j][2], acc[f][j][3]);
        }
    }
}

// ============================== scan kernels ===============================
__device__ __forceinline__ void lam_of(const float* __restrict__ nu_log,
                                       const float* __restrict__ th_log,
                                       int n, float& lr, float& li) {
    float mod = expf(-expf(nu_log[n]));
    float th  = expf(th_log[n]);
    lr = mod * cosf(th);
    li = mod * sinf(th);
}

__global__ __launch_bounds__(NST) void scan_phase1(
    const float* __restrict__ nu_log, const float* __restrict__ th_log)
{
    int b = blockIdx.x / (NCH - 1), c = blockIdx.x % (NCH - 1);
    int n = threadIdx.x;
    float lr, li; lam_of(nu_log, th_log, n, lr, li);
    float xr = 0.f, xi = 0.f;
    size_t base = ((size_t)b * SEQ + (size_t)c * CHUNK) * NST + n;
    float2 buf[16];
    #pragma unroll 1
    for (int g = 0; g < CHUNK / 16; g++) {
        #pragma unroll
        for (int i = 0; i < 16; i++)
            buf[i] = g_bu[base + (size_t)(g * 16 + i) * NST];
        #pragma unroll
        for (int i = 0; i < 16; i++) {
            float br = buf[i].x, bi = buf[i].y;
            float nxr = fmaf(lr, xr, fmaf(-li, xi, br));
            float nxi = fmaf(lr, xi, fmaf( li, xr, bi));
            xr = nxr; xi = nxi;
        }
    }
    g_part[(b * NCH + c) * NST + n] = make_float2(xr, xi);
}

__global__ __launch_bounds__(NST) void scan_phase2(
    const float* __restrict__ nu_log, const float* __restrict__ th_log)
{
    int b = blockIdx.x;
    int n = threadIdx.x;
    float lr, li; lam_of(nu_log, th_log, n, lr, li);
    float Lr = lr, Li = li;
    #pragma unroll
    for (int i = 0; i < 6; i++) {    // lam^64 = lam^CHUNK
        float nr = Lr * Lr - Li * Li;
        float ni = 2.f * Lr * Li;
        Lr = nr; Li = ni;
    }
    float sr = 0.f, si = 0.f;
    for (int c = 0; c < NCH; c++) {
        int idx = (b * NCH + c) * NST + n;
        float2 p = g_part[idx];
        g_part[idx] = make_float2(sr, si);   // state at chunk start
        float nsr = fmaf(Lr, sr, fmaf(-Li, si, p.x));
        float nsi = fmaf(Lr, si, fmaf( Li, sr, p.y));
        sr = nsr; si = nsi;
    }
}

// phase 3: replay chunk from its start state; write pre_t = x_{t-1} directly
// as bf16x2 hi/lo split planes (GEMM2's A operand format).
__global__ __launch_bounds__(NST) void scan_phase3(
    const float* __restrict__ nu_log, const float* __restrict__ th_log)
{
    int b = blockIdx.x / NCH, c = blockIdx.x % NCH;
    int n = threadIdx.x;
    float lr, li; lam_of(nu_log, th_log, n, lr, li);
    float2 s = g_part[(b * NCH + c) * NST + n];
    float xr = s.x, xi = s.y;
    size_t base = ((size_t)b * SEQ + (size_t)c * CHUNK) * NST + n;
    float2 buf[16];
    #pragma unroll 1
    for (int g = 0; g < CHUNK / 16; g++) {
        #pragma unroll
        for (int i = 0; i < 16; i++)
            buf[i] = g_bu[base + (size_t)(g * 16 + i) * NST];
        #pragma unroll
        for (int i = 0; i < 16; i++) {
            size_t off = base + (size_t)(g * 16 + i) * NST;
            uint32_t hi, lo; split2(xr, xi, hi, lo);
            g_pre16_hi[off] = hi;
            g_pre16_lo[off] = lo;
            float br = buf[i].x, bi = buf[i].y;
            float nxr = fmaf(lr, xr, fmaf(-li, xi, br));
            float nxi = fmaf(lr, xi, fmaf( li, xr, bi));
            xr = nxr; xi = nxi;
        }
    }
}

// ================================ launch ===================================
extern "C" void kernel_launch(void* const* d_in, const int* in_sizes, int n_in,
                              void* d_out, int out_size) {
    const float* u         = (const float*)d_in[0];
    const float* nu_log    = (const float*)d_in[1];
    const float* theta_log = (const float*)d_in[2];
    const float* gamma_log = (const float*)d_in[3];
    const float* Bre       = (const float*)d_in[4];
    const float* Bim       = (const float*)d_in[5];
    const float* Cre       = (const float*)d_in[6];
    const float* Cim       = (const float*)d_in[7];
    const float* Dm        = (const float*)d_in[8];
    float* y = (float*)d_out;

    cudaFuncSetAttribute(mma_gemm<0>,
                         cudaFuncAttributeMaxDynamicSharedMemorySize, SMEM_BYTES);
    cudaFuncSetAttribute(mma_gemm<1>,
                         cudaFuncAttributeMaxDynamicSharedMemorySize, SMEM_BYTES);

    prep_u<<<(MTOT * 64) / 256, 256>>>(u);
    prep_w<<<(512 * 64 + HOUT * 320 + 255) / 256, 256>>>(Bre, Bim, gamma_log,
                                                         Cre, Cim, Dm);

    // GEMM1: g_bu = gamma * (u @ [Bre|Bim]^T)
    dim3 gb(4, MTOT / 128);
    mma_gemm<0><<<gb, 256, SMEM_BYTES>>>(nullptr);

    scan_phase1<<<BSZ * (NCH - 1), NST>>>(nu_log, theta_log);
    scan_phase2<<<BSZ, NST>>>(nu_log, theta_log);
    scan_phase3<<<BSZ * NCH, NST>>>(nu_log, theta_log);

    // GEMM2: y = pre_re@Cre^T - pre_im@Cim^T + u@D^T  (K=640 concat)
    dim3 gy(1, MTOT / 128);
    mma_gemm<1><<<gy, 256, SMEM_BYTES>>>(y);
}

// round 6
// speedup vs baseline: 1.0108x; 1.0108x over previous
#include <cuda_runtime.h>
#include <math.h>
#include <stdint.h>

#define BSZ   16
#define SEQ   4096
#define NST   256
#define HIN   128
#define HOUT  128
#define MTOT  (BSZ*SEQ)      // 65536
#define CHUNK 64
#define NCH   (SEQ/CHUNK)    // 64

// ------------------------------ scratch -----------------------------------
__device__ float2   g_bu[(size_t)MTOT*NST];        // fp32 Bu (re,im), scan input
__device__ float2   g_part[BSZ*NCH*NST];
__device__ uint32_t g_pre16_hi[(size_t)MTOT*256];  // bf16x2 split pre-states
__device__ uint32_t g_pre16_lo[(size_t)MTOT*256];
__device__ uint32_t g_u16_hi[(size_t)MTOT*64];
__device__ uint32_t g_u16_lo[(size_t)MTOT*64];
__device__ uint32_t g_wbu16_hi[512*64];
__device__ uint32_t g_wbu16_lo[512*64];
__device__ uint32_t g_wy16_hi[HOUT*320];
__device__ uint32_t g_wy16_lo[HOUT*320];

__device__ __forceinline__ uint32_t packbf(float v0, float v1) {
    uint32_t r;
    asm("cvt.rn.bf16x2.f32 %0, %1, %2;" : "=r"(r) : "f"(v1), "f"(v0));
    return r;
}
__device__ __forceinline__ void split2(float v0, float v1,
                                       uint32_t& hi, uint32_t& lo) {
    hi = packbf(v0, v1);
    float h0 = __uint_as_float(hi << 16);
    float h1 = __uint_as_float(hi & 0xffff0000u);
    lo = packbf(v0 - h0, v1 - h1);
}

#define MMA_BF16(d, a, b0, b1)                                        \
    asm("mma.sync.aligned.m16n8k16.row.col.f32.bf16.bf16.f32 "        \
        "{%0,%1,%2,%3},{%4,%5,%6,%7},{%8,%9},{%0,%1,%2,%3};"          \
        : "+f"(d[0]), "+f"(d[1]), "+f"(d[2]), "+f"(d[3])              \
        : "r"(a[0]), "r"(a[1]), "r"(a[2]), "r"(a[3]), "r"(b0), "r"(b1))

#define LDSM4(r, addr)                                                \
    asm volatile("ldmatrix.sync.aligned.m8n8.x4.shared.b16 "          \
                 "{%0,%1,%2,%3}, [%4];"                               \
                 : "=r"((r)[0]), "=r"((r)[1]), "=r"((r)[2]), "=r"((r)[3]) \
                 : "r"(addr))

#define CP16(dst, src)                                                \
    asm volatile("cp.async.cg.shared.global [%0], [%1], 16;"          \
                 :: "r"(dst), "l"(src))
#define CP_COMMIT() asm volatile("cp.async.commit_group;" ::: "memory")

// smem: 2 buffers x 4 planes (Ahi,Alo,Whi,Wlo) x 128 rows x 36 words
// (144B row stride: 16B-aligned; ldmatrix 8-row phases hit all 32 banks).
#define RSTR   36
#define PLW    (128*RSTR)       // 4608 words/plane
#define BUFW   (4*PLW)          // 18432
#define SMEM_BYTES (2*BUFW*4)   // 147456

// ---------------------------------------------------------------------------
__global__ __launch_bounds__(256) void prep_w(
    const float* __restrict__ Bre, const float* __restrict__ Bim,
    const float* __restrict__ gamma_log,
    const float* __restrict__ Cre, const float* __restrict__ Cim,
    const float* __restrict__ Dm)
{
    int i = blockIdx.x * 256 + threadIdx.x;
    if (i < 512 * 64) {
        int n = i >> 6, j = i & 63;
        const float* B = (n & 1) ? Bim : Bre;
        float g = expf(gamma_log[n >> 1]);
        float v0 = B[(n >> 1) * HIN + 2 * j] * g;
        float v1 = B[(n >> 1) * HIN + 2 * j + 1] * g;
        uint32_t hi, lo; split2(v0, v1, hi, lo);
        g_wbu16_hi[i] = hi; g_wbu16_lo[i] = lo;
    } else if (i < 512 * 64 + HOUT * 320) {
        int t = i - 512 * 64;
        int o = t / 320, j = t % 320;
        float v0, v1;
        if (j < 256) { v0 = Cre[o * NST + j]; v1 = -Cim[o * NST + j]; }
        else { v0 = Dm[o * HIN + 2 * (j - 256)]; v1 = Dm[o * HIN + 2 * (j - 256) + 1]; }
        uint32_t hi, lo; split2(v0, v1, hi, lo);
        g_wy16_hi[t] = hi; g_wy16_lo[t] = lo;
    }
}

__global__ __launch_bounds__(256) void prep_u(const float* __restrict__ u)
{
    size_t i = (size_t)blockIdx.x * 256 + threadIdx.x;
    float2 v = ((const float2*)u)[i];
    uint32_t hi, lo; split2(v.x, v.y, hi, lo);
    g_u16_hi[i] = hi; g_u16_lo[i] = lo;
}

// ---------------------------------------------------------------------------
// Tensor-core GEMM: C[128m,128n] = A[128,K] x W[128n,K]^T, 3-product bf16
// split, cp.async staging, ldmatrix fragment loads.
// MODE 0: A=u16 (K=128); W=wbu16 tile; out -> g_bu fp32 (stride 512).
// MODE 1: A=[pre16|u16] (K=640); W=wy16; out -> y (stride 128).
// ---------------------------------------------------------------------------
template<int MODE>
__global__ __launch_bounds__(256, 1) void mma_gemm(float* __restrict__ y)
{
    extern __shared__ uint32_t sm[];
    uint32_t smb;
    asm("{ .reg .u64 t; cvta.to.shared.u64 t, %1; cvt.u32.u64 %0, t; }"
        : "=r"(smb) : "l"(sm));
    const int tid = threadIdx.x, lane = tid & 31, wid = tid >> 5;
    const int warp_m = (wid & 3) * 32, warp_n = (wid >> 2) * 64;
    const int ntile = (MODE == 0) ? blockIdx.x : 0;
    const int m0 = blockIdx.y * 128;
    const int NC = (MODE == 0) ? 2 : 10;

    float acc[2][8][4];
    #pragma unroll
    for (int f = 0; f < 2; f++)
        #pragma unroll
        for (int j = 0; j < 8; j++)
            #pragma unroll
            for (int q = 0; q < 4; q++) acc[f][j][q] = 0.f;

    auto cpy = [&](int c, int buf) {
        const uint32_t dbase = smb + (uint32_t)buf * BUFW * 4;
        if (tid < 128) {
            const int r = tid;
            const uint32_t *shi, *slo;
            if (MODE == 0) {
                size_t o = (size_t)(m0 + r) * 64 + c * 32;
                shi = g_u16_hi + o; slo = g_u16_lo + o;
            } else if (c < 8) {
                size_t o = (size_t)(m0 + r) * 256 + c * 32;
                shi = g_pre16_hi + o; slo = g_pre16_lo + o;
            } else {
                size_t o = (size_t)(m0 + r) * 64 + (c - 8) * 32;
                shi = g_u16_hi + o; slo = g_u16_lo + o;
            }
            uint32_t d0 = dbase + (r * RSTR) * 4;
            uint32_t d1 = dbase + (PLW + r * RSTR) * 4;
            #pragma unroll
            for (int i = 0; i < 8; i++) {
                CP16(d0 + i * 16, shi + i * 4);
                CP16(d1 + i * 16, slo + i * 4);
            }
        } else {
            const int r = tid - 128;
            const uint32_t *shi, *slo;
            if (MODE == 0) {
                size_t o = (size_t)(ntile * 128 + r) * 64 + c * 32;
                shi = g_wbu16_hi + o; slo = g_wbu16_lo + o;
            } else {
                size_t o = (size_t)r * 320 + c * 32;
                shi = g_wy16_hi + o; slo = g_wy16_lo + o;
            }
            uint32_t d0 = dbase + (2 * PLW + r * RSTR) * 4;
            uint32_t d1 = dbase + (3 * PLW + r * RSTR) * 4;
            #pragma unroll
            for (int i = 0; i < 8; i++) {
                CP16(d0 + i * 16, shi + i * 4);
                CP16(d1 + i * 16, slo + i * 4);
            }
        }
    };

    // per-lane ldmatrix base offsets (byte offsets inside a buffer)
    // A (16x16 per (f,ks)): lanes 0-15 -> rows, lanes 16-31 -> same rows @ +16B
    const uint32_t a_off = (uint32_t)(warp_m + (lane & 15)) * (RSTR * 4)
                         + ((lane >> 4) * 16);
    // B (two n8k16 per x4): groups of 8 lanes -> (n0-7,k0) (n0-7,k8) (n8-15,k0) (n8-15,k8)
    const int bg = lane >> 3;
    const uint32_t b_off = (uint32_t)(warp_n + ((bg >> 1) * 8) + (lane & 7)) * (RSTR * 4)
                         + ((bg & 1) * 16) + 2 * PLW * 4;

    auto comp = [&](int buf) {
        const uint32_t bb = smb + (uint32_t)buf * BUFW * 4;
        const uint32_t a_hi = bb + a_off, a_lo = a_hi + PLW * 4;
        const uint32_t w_hi = bb + b_off, w_lo = w_hi + PLW * 4;
        #pragma unroll
        for (int ks = 0; ks < 4; ks++) {
            const uint32_t kb = ks * 32;
            uint32_t ah[2][4], al[2][4];
            #pragma unroll
            for (int f = 0; f < 2; f++) {
                LDSM4(ah[f], a_hi + f * (16 * RSTR * 4) + kb);
                LDSM4(al[f], a_lo + f * (16 * RSTR * 4) + kb);
            }
            #pragma unroll
            for (int p = 0; p < 4; p++) {
                uint32_t bh[4], bl[4];
                LDSM4(bh, w_hi + p * (16 * RSTR * 4) + kb);
                LDSM4(bl, w_lo + p * (16 * RSTR * 4) + kb);
                #pragma unroll
                for (int jj = 0; jj < 2; jj++) {
                    const int j = 2 * p + jj;
                    #pragma unroll
                    for (int f = 0; f < 2; f++) {
                        MMA_BF16(acc[f][j], ah[f], bh[2*jj], bh[2*jj+1]);
                        MMA_BF16(acc[f][j], ah[f], bl[2*jj], bl[2*jj+1]);
                        MMA_BF16(acc[f][j], al[f], bh[2*jj], bh[2*jj+1]);
                    }
                }
            }
        }
    };

    cpy(0, 0); CP_COMMIT();
    cpy(1, 1); CP_COMMIT();
    #pragma unroll 1
    for (int c = 0; c < NC; c++) {
        if (c + 1 < NC) asm volatile("cp.async.wait_group 1;" ::: "memory");
        else            asm volatile("cp.async.wait_group 0;" ::: "memory");
        __syncthreads();
        comp(c & 1);
        __syncthreads();
        if (c + 2 < NC) { cpy(c + 2, c & 1); CP_COMMIT(); }
    }

    float* dst;
    int stride;
    if (MODE == 0) { dst = (float*)g_bu + (size_t)ntile * 128; stride = 512; }
    else           { dst = y;                                   stride = HOUT; }
    #pragma unroll
    for (int f = 0; f < 2; f++) {
        const int m = m0 + warp_m + f * 16 + (lane >> 2);
        #pragma unroll
        for (int j = 0; j < 8; j++) {
            const int n = warp_n + j * 8 + (lane & 3) * 2;
            *(float2*)(dst + (size_t)m * stride + n) =
                make_float2(acc[f][j][0], acc[f][j][1]);
            *(float2*)(dst + (size_t)(m + 8) * stride + n) =
                make_float2(acc[f][j][2], acc[f][j][3]);
        }
    }
}

// ============================== scan kernels ===============================
__device__ __forceinline__ void lam_of(const float* __restrict__ nu_log,
                                       const float* __restrict__ th_log,
                                       int n, float& lr, float& li) {
    float mod = expf(-expf(nu_log[n]));
    float th  = expf(th_log[n]);
    lr = mod * cosf(th);
    li = mod * sinf(th);
}

__global__ __launch_bounds__(NST) void scan_phase1(
    const float* __restrict__ nu_log, const float* __restrict__ th_log)
{
    int b = blockIdx.x / (NCH - 1), c = blockIdx.x % (NCH - 1);
    int n = threadIdx.x;
    float lr, li; lam_of(nu_log, th_log, n, lr, li);
    float xr = 0.f, xi = 0.f;
    size_t base = ((size_t)b * SEQ + (size_t)c * CHUNK) * NST + n;
    float2 buf[16];
    #pragma unroll 1
    for (int g = 0; g < CHUNK / 16; g++) {
        #pragma unroll
        for (int i = 0; i < 16; i++)
            buf[i] = g_bu[base + (size_t)(g * 16 + i) * NST];
        #pragma unroll
        for (int i = 0; i < 16; i++) {
            float br = buf[i].x, bi = buf[i].y;
            float nxr = fmaf(lr, xr, fmaf(-li, xi, br));
            float nxi = fmaf(lr, xi, fmaf( li, xr, bi));
            xr = nxr; xi = nxi;
        }
    }
    g_part[(b * NCH + c) * NST + n] = make_float2(xr, xi);
}

__global__ __launch_bounds__(NST) void scan_phase2(
    const float* __restrict__ nu_log, const float* __restrict__ th_log)
{
    int b = blockIdx.x;
    int n = threadIdx.x;
    float lr, li; lam_of(nu_log, th_log, n, lr, li);
    float Lr = lr, Li = li;
    #pragma unroll
    for (int i = 0; i < 6; i++) {    // lam^64 = lam^CHUNK
        float nr = Lr * Lr - Li * Li;
        float ni = 2.f * Lr * Li;
        Lr = nr; Li = ni;
    }
    float sr = 0.f, si = 0.f;
    float2 buf[16];
    #pragma unroll 1
    for (int g = 0; g < NCH / 16; g++) {
        #pragma unroll
        for (int i = 0; i < 16; i++)
            buf[i] = g_part[(b * NCH + g * 16 + i) * NST + n];
        #pragma unroll
        for (int i = 0; i < 16; i++) {
            int idx = (b * NCH + g * 16 + i) * NST + n;
            g_part[idx] = make_float2(sr, si);   // state at chunk start
            float nsr = fmaf(Lr, sr, fmaf(-Li, si, buf[i].x));
            float nsi = fmaf(Lr, si, fmaf( Li, sr, buf[i].y));
            sr = nsr; si = nsi;
        }
    }
}

__global__ __launch_bounds__(NST) void scan_phase3(
    const float* __restrict__ nu_log, const float* __restrict__ th_log)
{
    int b = blockIdx.x / NCH, c = blockIdx.x % NCH;
    int n = threadIdx.x;
    float lr, li; lam_of(nu_log, th_log, n, lr, li);
    float2 s = g_part[(b * NCH + c) * NST + n];
    float xr = s.x, xi = s.y;
    size_t base = ((size_t)b * SEQ + (size_t)c * CHUNK) * NST + n;
    float2 buf[16];
    #pragma unroll 1
    for (int g = 0; g < CHUNK / 16; g++) {
        #pragma unroll
        for (int i = 0; i < 16; i++)
            buf[i] = g_bu[base + (size_t)(g * 16 + i) * NST];
        #pragma unroll
        for (int i = 0; i < 16; i++) {
            size_t off = base + (size_t)(g * 16 + i) * NST;
            uint32_t hi, lo; split2(xr, xi, hi, lo);
            g_pre16_hi[off] = hi;
            g_pre16_lo[off] = lo;
            float br = buf[i].x, bi = buf[i].y;
            float nxr = fmaf(lr, xr, fmaf(-li, xi, br));
            float nxi = fmaf(lr, xi, fmaf( li, xr, bi));
            xr = nxr; xi = nxi;
        }
    }
}

// ================================ launch ===================================
extern "C" void kernel_launch(void* const* d_in, const int* in_sizes, int n_in,
                              void* d_out, int out_size) {
    const float* u         = (const float*)d_in[0];
    const float* nu_log    = (const float*)d_in[1];
    const float* theta_log = (const float*)d_in[2];
    const float* gamma_log = (const float*)d_in[3];
    const float* Bre       = (const float*)d_in[4];
    const float* Bim       = (const float*)d_in[5];
    const float* Cre       = (const float*)d_in[6];
    const float* Cim       = (const float*)d_in[7];
    const float* Dm        = (const float*)d_in[8];
    float* y = (float*)d_out;

    cudaFuncSetAttribute(mma_gemm<0>,
                         cudaFuncAttributeMaxDynamicSharedMemorySize, SMEM_BYTES);
    cudaFuncSetAttribute(mma_gemm<1>,
                         cudaFuncAttributeMaxDynamicSharedMemorySize, SMEM_BYTES);

    prep_u<<<(MTOT * 64) / 256, 256>>>(u);
    prep_w<<<(512 * 64 + HOUT * 320 + 255) / 256, 256>>>(Bre, Bim, gamma_log,
                                                         Cre, Cim, Dm);

    dim3 gb(4, MTOT / 128);
    mma_gemm<0><<<gb, 256, SMEM_BYTES>>>(nullptr);

    scan_phase1<<<BSZ * (NCH - 1), NST>>>(nu_log, theta_log);
    scan_phase2<<<BSZ, NST>>>(nu_log, theta_log);
    scan_phase3<<<BSZ * NCH, NST>>>(nu_log, theta_log);

    dim3 gy(1, MTOT / 128);
    mma_gemm<1><<<gy, 256, SMEM_BYTES>>>(y);
}

// round 8
// speedup vs baseline: 1.0979x; 1.0861x over previous
#include <cuda_runtime.h>
#include <math.h>
#include <stdint.h>

#define BSZ   16
#define SEQ   4096
#define NST   256
#define HIN   128
#define HOUT  128
#define MTOT  (BSZ*SEQ)      // 65536
#define CHUNK 64
#define NCH   (SEQ/CHUNK)    // 64

// ------------------------------ scratch -----------------------------------
__device__ float2   g_bu[(size_t)MTOT*NST];        // fp32 Bu (re,im), scan input
__device__ float2   g_part[BSZ*NCH*NST];
__device__ uint32_t g_pre16_hi[(size_t)MTOT*256];  // bf16x2 split pre-states
__device__ uint32_t g_pre16_lo[(size_t)MTOT*256];
__device__ uint32_t g_u16_hi[(size_t)MTOT*64];
__device__ uint32_t g_u16_lo[(size_t)MTOT*64];
__device__ uint32_t g_wbu16_hi[512*64];
__device__ uint32_t g_wbu16_lo[512*64];
__device__ uint32_t g_wy16_hi[HOUT*320];
__device__ uint32_t g_wy16_lo[HOUT*320];

__device__ __forceinline__ uint32_t packbf(float v0, float v1) {
    uint32_t r;
    asm("cvt.rn.bf16x2.f32 %0, %1, %2;" : "=r"(r) : "f"(v1), "f"(v0));
    return r;
}
__device__ __forceinline__ void split2(float v0, float v1,
                                       uint32_t& hi, uint32_t& lo) {
    hi = packbf(v0, v1);
    float h0 = __uint_as_float(hi << 16);
    float h1 = __uint_as_float(hi & 0xffff0000u);
    lo = packbf(v0 - h0, v1 - h1);
}

#define MMA_BF16(d, a, b0, b1)                                        \
    asm("mma.sync.aligned.m16n8k16.row.col.f32.bf16.bf16.f32 "        \
        "{%0,%1,%2,%3},{%4,%5,%6,%7},{%8,%9},{%0,%1,%2,%3};"          \
        : "+f"(d[0]), "+f"(d[1]), "+f"(d[2]), "+f"(d[3])              \
        : "r"(a[0]), "r"(a[1]), "r"(a[2]), "r"(a[3]), "r"(b0), "r"(b1))

#define LDSM4(r, addr)                                                \
    asm volatile("ldmatrix.sync.aligned.m8n8.x4.shared.b16 "          \
                 "{%0,%1,%2,%3}, [%4];"                               \
                 : "=r"((r)[0]), "=r"((r)[1]), "=r"((r)[2]), "=r"((r)[3]) \
                 : "r"(addr))

#define CP16(dst, src)                                                \
    asm volatile("cp.async.cg.shared.global [%0], [%1], 16;"          \
                 :: "r"(dst), "l"(src))
#define CP_COMMIT() asm volatile("cp.async.commit_group;" ::: "memory")

// smem: 2 buffers x 4 planes (Ahi,Alo,Whi,Wlo) x 128 rows x 20 words.
// 16 data words/row (one 32-element bf16 K-chunk) + 4 pad.
// 80B row stride: 16B-aligned; ldmatrix 8-row phases conflict-free.
#define CHW    16
#define RSTR   20
#define PLW    (128*RSTR)       // 2560 words/plane
#define BUFW   (4*PLW)          // 10240
#define SMEM_BYTES (2*BUFW*4)   // 81920 -> 2 CTAs/SM

// ---------------------------------------------------------------------------
__global__ __launch_bounds__(256) void prep_w(
    const float* __restrict__ Bre, const float* __restrict__ Bim,
    const float* __restrict__ gamma_log,
    const float* __restrict__ Cre, const float* __restrict__ Cim,
    const float* __restrict__ Dm)
{
    int i = blockIdx.x * 256 + threadIdx.x;
    if (i < 512 * 64) {
        int n = i >> 6, j = i & 63;
        const float* B = (n & 1) ? Bim : Bre;
        float g = expf(gamma_log[n >> 1]);
        float v0 = B[(n >> 1) * HIN + 2 * j] * g;
        float v1 = B[(n >> 1) * HIN + 2 * j + 1] * g;
        uint32_t hi, lo; split2(v0, v1, hi, lo);
        g_wbu16_hi[i] = hi; g_wbu16_lo[i] = lo;
    } else if (i < 512 * 64 + HOUT * 320) {
        int t = i - 512 * 64;
        int o = t / 320, j = t % 320;
        float v0, v1;
        if (j < 256) { v0 = Cre[o * NST + j]; v1 = -Cim[o * NST + j]; }
        else { v0 = Dm[o * HIN + 2 * (j - 256)]; v1 = Dm[o * HIN + 2 * (j - 256) + 1]; }
        uint32_t hi, lo; split2(v0, v1, hi, lo);
        g_wy16_hi[t] = hi; g_wy16_lo[t] = lo;
    }
}

__global__ __launch_bounds__(256) void prep_u(const float* __restrict__ u)
{
    size_t i = (size_t)blockIdx.x * 256 + threadIdx.x;
    float2 v = ((const float2*)u)[i];
    uint32_t hi, lo; split2(v.x, v.y, hi, lo);
    g_u16_hi[i] = hi; g_u16_lo[i] = lo;
}

// ---------------------------------------------------------------------------
// Tensor-core GEMM: C[128m,128n] = A[128,K] x W[128n,K]^T, 3-product bf16
// split, cp.async double-buffer, ldmatrix fragments, 2 CTAs/SM.
// MODE 0: A=u16 (K=128, 4 chunks); W=wbu16 tile; out -> g_bu fp32 (stride 512).
// MODE 1: A=[pre16|u16] (K=640, 20 chunks); W=wy16; out -> y (stride 128).
// ---------------------------------------------------------------------------
template<int MODE>
__global__ __launch_bounds__(256, 2) void mma_gemm(float* __restrict__ y)
{
    extern __shared__ uint32_t sm[];
    uint32_t smb;
    asm("{ .reg .u64 t; cvta.to.shared.u64 t, %1; cvt.u32.u64 %0, t; }"
        : "=r"(smb) : "l"(sm));
    const int tid = threadIdx.x, lane = tid & 31, wid = tid >> 5;
    const int warp_m = (wid & 3) * 32, warp_n = (wid >> 2) * 64;
    const int ntile = (MODE == 0) ? blockIdx.x : 0;
    const int m0 = blockIdx.y * 128;
    const int NC = (MODE == 0) ? 4 : 20;

    float acc[2][8][4];
    #pragma unroll
    for (int f = 0; f < 2; f++)
        #pragma unroll
        for (int j = 0; j < 8; j++)
            #pragma unroll
            for (int q = 0; q < 4; q++) acc[f][j][q] = 0.f;

    // stage chunk c (16 words) into buffer buf: threads<128 -> A row tid,
    // else W row tid-128; 4x16B hi + 4x16B lo.
    auto cpy = [&](int c, int buf) {
        const uint32_t dbase = smb + (uint32_t)buf * BUFW * 4;
        if (tid < 128) {
            const int r = tid;
            const uint32_t *shi, *slo;
            if (MODE == 0) {
                size_t o = (size_t)(m0 + r) * 64 + c * CHW;
                shi = g_u16_hi + o; slo = g_u16_lo + o;
            } else if (c < 16) {
                size_t o = (size_t)(m0 + r) * 256 + c * CHW;
                shi = g_pre16_hi + o; slo = g_pre16_lo + o;
            } else {
                size_t o = (size_t)(m0 + r) * 64 + (c - 16) * CHW;
                shi = g_u16_hi + o; slo = g_u16_lo + o;
            }
            uint32_t d0 = dbase + (r * RSTR) * 4;
            uint32_t d1 = dbase + (PLW + r * RSTR) * 4;
            #pragma unroll
            for (int i = 0; i < 4; i++) {
                CP16(d0 + i * 16, shi + i * 4);
                CP16(d1 + i * 16, slo + i * 4);
            }
        } else {
            const int r = tid - 128;
            const uint32_t *shi, *slo;
            if (MODE == 0) {
                size_t o = (size_t)(ntile * 128 + r) * 64 + c * CHW;
                shi = g_wbu16_hi + o; slo = g_wbu16_lo + o;
            } else {
                size_t o = (size_t)r * 320 + c * CHW;
                shi = g_wy16_hi + o; slo = g_wy16_lo + o;
            }
            uint32_t d0 = dbase + (2 * PLW + r * RSTR) * 4;
            uint32_t d1 = dbase + (3 * PLW + r * RSTR) * 4;
            #pragma unroll
            for (int i = 0; i < 4; i++) {
                CP16(d0 + i * 16, shi + i * 4);
                CP16(d1 + i * 16, slo + i * 4);
            }
        }
    };

    // ldmatrix lane offsets (bytes within a buffer)
    const uint32_t a_off = (uint32_t)(warp_m + (lane & 15)) * (RSTR * 4)
                         + ((lane >> 4) * 16);
    const int bg = lane >> 3;
    const uint32_t b_off = (uint32_t)(warp_n + ((bg >> 1) * 8) + (lane & 7)) * (RSTR * 4)
                         + ((bg & 1) * 16) + 2 * PLW * 4;

    auto comp = [&](int buf) {
        const uint32_t bb = smb + (uint32_t)buf * BUFW * 4;
        const uint32_t a_hi = bb + a_off, a_lo = a_hi + PLW * 4;
        const uint32_t w_hi = bb + b_off, w_lo = w_hi + PLW * 4;
        #pragma unroll
        for (int ks = 0; ks < 2; ks++) {
            const uint32_t kb = ks * 32;
            uint32_t ah[2][4], al[2][4];
            #pragma unroll
            for (int f = 0; f < 2; f++) {
                LDSM4(ah[f], a_hi + f * (16 * RSTR * 4) + kb);
                LDSM4(al[f], a_lo + f * (16 * RSTR * 4) + kb);
            }
            #pragma unroll
            for (int p = 0; p < 4; p++) {
                uint32_t bh[4], bl[4];
                LDSM4(bh, w_hi + p * (16 * RSTR * 4) + kb);
                LDSM4(bl, w_lo + p * (16 * RSTR * 4) + kb);
                #pragma unroll
                for (int jj = 0; jj < 2; jj++) {
                    const int j = 2 * p + jj;
                    #pragma unroll
                    for (int f = 0; f < 2; f++) {
                        MMA_BF16(acc[f][j], ah[f], bh[2*jj], bh[2*jj+1]);
                        MMA_BF16(acc[f][j], ah[f], bl[2*jj], bl[2*jj+1]);
                        MMA_BF16(acc[f][j], al[f], bh[2*jj], bh[2*jj+1]);
                    }
                }
            }
        }
    };

    cpy(0, 0); CP_COMMIT();
    cpy(1, 1); CP_COMMIT();
    #pragma unroll 1
    for (int c = 0; c < NC; c++) {
        if (c + 1 < NC) asm volatile("cp.async.wait_group 1;" ::: "memory");
        else            asm volatile("cp.async.wait_group 0;" ::: "memory");
        __syncthreads();
        comp(c & 1);
        __syncthreads();
        if (c + 2 < NC) { cpy(c + 2, c & 1); CP_COMMIT(); }
    }

    float* dst;
    int stride;
    if (MODE == 0) { dst = (float*)g_bu + (size_t)ntile * 128; stride = 512; }
    else           { dst = y;                                   stride = HOUT; }
    #pragma unroll
    for (int f = 0; f < 2; f++) {
        const int m = m0 + warp_m + f * 16 + (lane >> 2);
        #pragma unroll
        for (int j = 0; j < 8; j++) {
            const int n = warp_n + j * 8 + (lane & 3) * 2;
            *(float2*)(dst + (size_t)m * stride + n) =
                make_float2(acc[f][j][0], acc[f][j][1]);
            *(float2*)(dst + (size_t)(m + 8) * stride + n) =
                make_float2(acc[f][j][2], acc[f][j][3]);
        }
    }
}

// ============================== scan kernels ===============================
__device__ __forceinline__ void lam_of(const float* __restrict__ nu_log,
                                       const float* __restrict__ th_log,
                                       int n, float& lr, float& li) {
    float mod = expf(-expf(nu_log[n]));
    float th  = expf(th_log[n]);
    lr = mod * cosf(th);
    li = mod * sinf(th);
}

__global__ __launch_bounds__(NST) void scan_phase1(
    const float* __restrict__ nu_log, const float* __restrict__ th_log)
{
    int b = blockIdx.x / (NCH - 1), c = blockIdx.x % (NCH - 1);
    int n = threadIdx.x;
    float lr, li; lam_of(nu_log, th_log, n, lr, li);
    float xr = 0.f, xi = 0.f;
    size_t base = ((size_t)b * SEQ + (size_t)c * CHUNK) * NST + n;
    float2 buf[16];
    #pragma unroll 1
    for (int g = 0; g < CHUNK / 16; g++) {
        #pragma unroll
        for (int i = 0; i < 16; i++)
            buf[i] = g_bu[base + (size_t)(g * 16 + i) * NST];
        #pragma unroll
        for (int i = 0; i < 16; i++) {
            float br = buf[i].x, bi = buf[i].y;
            float nxr = fmaf(lr, xr, fmaf(-li, xi, br));
            float nxi = fmaf(lr, xi, fmaf( li, xr, bi));
            xr = nxr; xi = nxi;
        }
    }
    g_part[(b * NCH + c) * NST + n] = make_float2(xr, xi);
}

__global__ __launch_bounds__(NST) void scan_phase2(
    const float* __restrict__ nu_log, const float* __restrict__ th_log)
{
    int b = blockIdx.x;
    int n = threadIdx.x;
    float lr, li; lam_of(nu_log, th_log, n, lr, li);
    float Lr = lr, Li = li;
    #pragma unroll
    for (int i = 0; i < 6; i++) {
        float nr = Lr * Lr - Li * Li;
        float ni = 2.f * Lr * Li;
        Lr = nr; Li = ni;
    }
    float sr = 0.f, si = 0.f;
    float2 buf[16];
    #pragma unroll 1
    for (int g = 0; g < NCH / 16; g++) {
        #pragma unroll
        for (int i = 0; i < 16; i++)
            buf[i] = g_part[(b * NCH + g * 16 + i) * NST + n];
        #pragma unroll
        for (int i = 0; i < 16; i++) {
            int idx = (b * NCH + g * 16 + i) * NST + n;
            g_part[idx] = make_float2(sr, si);
            float nsr = fmaf(Lr, sr, fmaf(-Li, si, buf[i].x));
            float nsi = fmaf(Lr, si, fmaf( Li, sr, buf[i].y));
            sr = nsr; si = nsi;
        }
    }
}

__global__ __launch_bounds__(NST) void scan_phase3(
    const float* __restrict__ nu_log, const float* __restrict__ th_log)
{
    int b = blockIdx.x / NCH, c = blockIdx.x % NCH;
    int n = threadIdx.x;
    float lr, li; lam_of(nu_log, th_log, n, lr, li);
    float2 s = g_part[(b * NCH + c) * NST + n];
    float xr = s.x, xi = s.y;
    size_t base = ((size_t)b * SEQ + (size_t)c * CHUNK) * NST + n;
    float2 buf[16];
    #pragma unroll 1
    for (int g = 0; g < CHUNK / 16; g++) {
        #pragma unroll
        for (int i = 0; i < 16; i++)
            buf[i] = g_bu[base + (size_t)(g * 16 + i) * NST];
        #pragma unroll
        for (int i = 0; i < 16; i++) {
            size_t off = base + (size_t)(g * 16 + i) * NST;
            uint32_t hi, lo; split2(xr, xi, hi, lo);
            g_pre16_hi[off] = hi;
            g_pre16_lo[off] = lo;
            float br = buf[i].x, bi = buf[i].y;
            float nxr = fmaf(lr, xr, fmaf(-li, xi, br));
            float nxi = fmaf(lr, xi, fmaf( li, xr, bi));
            xr = nxr; xi = nxi;
        }
    }
}

// ================================ launch ===================================
extern "C" void kernel_launch(void* const* d_in, const int* in_sizes, int n_in,
                              void* d_out, int out_size) {
    const float* u         = (const float*)d_in[0];
    const float* nu_log    = (const float*)d_in[1];
    const float* theta_log = (const float*)d_in[2];
    const float* gamma_log = (const float*)d_in[3];
    const float* Bre       = (const float*)d_in[4];
    const float* Bim       = (const float*)d_in[5];
    const float* Cre       = (const float*)d_in[6];
    const float* Cim       = (const float*)d_in[7];
    const float* Dm        = (const float*)d_in[8];
    float* y = (float*)d_out;

    // Required for >48KB dynamic smem; host-side attribute set, not a stream
    // op, so it's graph-capture safe (same pattern passed in R5/R6).
    static int attr_done = 0;
    if (!attr_done) {
        cudaFuncSetAttribute(mma_gemm<0>,
                             cudaFuncAttributeMaxDynamicSharedMemorySize, SMEM_BYTES);
        cudaFuncSetAttribute(mma_gemm<1>,
                             cudaFuncAttributeMaxDynamicSharedMemorySize, SMEM_BYTES);
        attr_done = 1;
    }

    prep_u<<<(MTOT * 64) / 256, 256>>>(u);
    prep_w<<<(512 * 64 + HOUT * 320 + 255) / 256, 256>>>(Bre, Bim, gamma_log,
                                                         Cre, Cim, Dm);

    dim3 gb(4, MTOT / 128);
    mma_gemm<0><<<gb, 256, SMEM_BYTES>>>(nullptr);

    scan_phase1<<<BSZ * (NCH - 1), NST>>>(nu_log, theta_log);
    scan_phase2<<<BSZ, NST>>>(nu_log, theta_log);
    scan_phase3<<<BSZ * NCH, NST>>>(nu_log, theta_log);

    dim3 gy(1, MTOT / 128);
    mma_gemm<1><<<gy, 256, SMEM_BYTES>>>(y);
}

// round 9
// speedup vs baseline: 1.4250x; 1.2979x over previous
#include <cuda_runtime.h>
#include <cuda_fp16.h>
#include <math.h>
#include <stdint.h>

#define BSZ   16
#define SEQ   4096
#define NST   256
#define HIN   128
#define HOUT  128
#define MTOT  (BSZ*SEQ)      // 65536
#define CHUNK 64
#define NCH   (SEQ/CHUNK)    // 64

// ------------------------------ scratch -----------------------------------
__device__ float2   g_bu[(size_t)MTOT*NST];        // fp32 Bu (re,im), scan input
__device__ float2   g_part[BSZ*NCH*NST];
__device__ uint32_t g_pre16[(size_t)MTOT*256];     // f16x2 pre-states (single)
__device__ uint32_t g_u16_hi[(size_t)MTOT*64];     // f16x2 u split (GEMM1 A)
__device__ uint32_t g_u16_lo[(size_t)MTOT*64];     //   (hi also = GEMM2 tail A)
__device__ uint32_t g_wbu16[512*64];               // f16x2 wbu (single)
__device__ uint32_t g_wy16_hi[HOUT*320];           // f16x2 wy split
__device__ uint32_t g_wy16_lo[HOUT*320];

__device__ __forceinline__ uint32_t packf16(float v0, float v1) {
    uint32_t r;
    asm("cvt.rn.f16x2.f32 %0, %1, %2;" : "=r"(r) : "f"(v1), "f"(v0));
    return r;   // v0 in lower half
}
__device__ __forceinline__ void split2h(float v0, float v1,
                                        uint32_t& hi, uint32_t& lo) {
    hi = packf16(v0, v1);
    __half2 h = *reinterpret_cast<__half2*>(&hi);
    float2 hf = __half22float2(h);
    lo = packf16(v0 - hf.x, v1 - hf.y);
}

#define MMA_F16(d, a, b0, b1)                                         \
    asm("mma.sync.aligned.m16n8k16.row.col.f32.f16.f16.f32 "          \
        "{%0,%1,%2,%3},{%4,%5,%6,%7},{%8,%9},{%0,%1,%2,%3};"          \
        : "+f"(d[0]), "+f"(d[1]), "+f"(d[2]), "+f"(d[3])              \
        : "r"(a[0]), "r"(a[1]), "r"(a[2]), "r"(a[3]), "r"(b0), "r"(b1))

#define LDSM4(r, addr)                                                \
    asm volatile("ldmatrix.sync.aligned.m8n8.x4.shared.b16 "          \
                 "{%0,%1,%2,%3}, [%4];"                               \
                 : "=r"((r)[0]), "=r"((r)[1]), "=r"((r)[2]), "=r"((r)[3]) \
                 : "r"(addr))

#define CP16(dst, src)                                                \
    asm volatile("cp.async.cg.shared.global [%0], [%1], 16;"          \
                 :: "r"(dst), "l"(src))
#define CP_COMMIT() asm volatile("cp.async.commit_group;" ::: "memory")

// smem: 2 buffers x 3 planes x 128 rows x 20 words (80B stride,
// 16B-aligned, ldmatrix-conflict-free).
// MODE0 planes: [u_hi, u_lo, wbu]   MODE1 planes: [A(pre|u), wy_hi, wy_lo]
#define CHW    16
#define RSTR   20
#define PLW    (128*RSTR)       // 2560 words/plane
#define BUFW   (3*PLW)          // 7680
#define SMEM_BYTES (2*BUFW*4)   // 61440 -> 2 CTAs/SM

// ---------------------------------------------------------------------------
// prep: one kernel builds all fp16 operand planes.
//   [0, NU)            : u split hi/lo           (NU = MTOT*64 words)
//   [NU, NU+32768)     : wbu single
//   [NU+32768, +40960) : wy split hi/lo
// ---------------------------------------------------------------------------
#define NU (MTOT*64)
__global__ __launch_bounds__(256) void prep_all(
    const float* __restrict__ u,
    const float* __restrict__ Bre, const float* __restrict__ Bim,
    const float* __restrict__ gamma_log,
    const float* __restrict__ Cre, const float* __restrict__ Cim,
    const float* __restrict__ Dm)
{
    size_t i = (size_t)blockIdx.x * 256 + threadIdx.x;
    if (i < (size_t)NU) {
        float2 v = ((const float2*)u)[i];
        uint32_t hi, lo; split2h(v.x, v.y, hi, lo);
        g_u16_hi[i] = hi; g_u16_lo[i] = lo;
    } else if (i < (size_t)NU + 512 * 64) {
        int t = (int)(i - NU);
        int n = t >> 6, j = t & 63;
        const float* B = (n & 1) ? Bim : Bre;
        float g = expf(gamma_log[n >> 1]);
        float v0 = B[(n >> 1) * HIN + 2 * j] * g;
        float v1 = B[(n >> 1) * HIN + 2 * j + 1] * g;
        g_wbu16[t] = packf16(v0, v1);
    } else if (i < (size_t)NU + 512 * 64 + HOUT * 320) {
        int t = (int)(i - NU - 512 * 64);
        int o = t / 320, j = t % 320;
        float v0, v1;
        if (j < 256) { v0 = Cre[o * NST + j]; v1 = -Cim[o * NST + j]; }
        else { v0 = Dm[o * HIN + 2 * (j - 256)]; v1 = Dm[o * HIN + 2 * (j - 256) + 1]; }
        uint32_t hi, lo; split2h(v0, v1, hi, lo);
        g_wy16_hi[t] = hi; g_wy16_lo[t] = lo;
    }
}

// ---------------------------------------------------------------------------
// 2-product fp16 tensor-core GEMM: C[128m,128n] = A[128,K] x W[128n,K]^T.
// MODE 0: A = u (split hi+lo), W = wbu (single); K=128, out -> g_bu fp32.
// MODE 1: A = [pre|u_hi] (single), W = wy (split hi+lo); K=640, out -> y.
// ---------------------------------------------------------------------------
template<int MODE>
__global__ __launch_bounds__(256, 2) void mma_gemm(float* __restrict__ y)
{
    extern __shared__ uint32_t sm[];
    uint32_t smb;
    asm("{ .reg .u64 t; cvta.to.shared.u64 t, %1; cvt.u32.u64 %0, t; }"
        : "=r"(smb) : "l"(sm));
    const int tid = threadIdx.x, lane = tid & 31, wid = tid >> 5;
    const int warp_m = (wid & 3) * 32, warp_n = (wid >> 2) * 64;
    const int ntile = (MODE == 0) ? blockIdx.x : 0;
    const int m0 = blockIdx.y * 128;
    const int NC = (MODE == 0) ? 4 : 20;

    float acc[2][8][4];
    #pragma unroll
    for (int f = 0; f < 2; f++)
        #pragma unroll
        for (int j = 0; j < 8; j++)
            #pragma unroll
            for (int q = 0; q < 4; q++) acc[f][j][q] = 0.f;

    auto cpy = [&](int c, int buf) {
        const uint32_t dbase = smb + (uint32_t)buf * BUFW * 4;
        if (tid < 128) {
            const int r = tid;
            if (MODE == 0) {              // A = u split: planes 0,1
                size_t o = (size_t)(m0 + r) * 64 + c * CHW;
                uint32_t d0 = dbase + (r * RSTR) * 4;
                uint32_t d1 = dbase + (PLW + r * RSTR) * 4;
                #pragma unroll
                for (int i = 0; i < 4; i++) {
                    CP16(d0 + i * 16, g_u16_hi + o + i * 4);
                    CP16(d1 + i * 16, g_u16_lo + o + i * 4);
                }
            } else {                      // A single: plane 0
                const uint32_t* s;
                if (c < 16) s = g_pre16 + (size_t)(m0 + r) * 256 + c * CHW;
                else        s = g_u16_hi + (size_t)(m0 + r) * 64 + (c - 16) * CHW;
                uint32_t d0 = dbase + (r * RSTR) * 4;
                #pragma unroll
                for (int i = 0; i < 4; i++) CP16(d0 + i * 16, s + i * 4);
            }
        } else {
            const int r = tid - 128;
            if (MODE == 0) {              // W single: plane 2
                size_t o = (size_t)(ntile * 128 + r) * 64 + c * CHW;
                uint32_t d2 = dbase + (2 * PLW + r * RSTR) * 4;
                #pragma unroll
                for (int i = 0; i < 4; i++) CP16(d2 + i * 16, g_wbu16 + o + i * 4);
            } else {                      // W split: planes 1,2
                size_t o = (size_t)r * 320 + c * CHW;
                uint32_t d1 = dbase + (PLW + r * RSTR) * 4;
                uint32_t d2 = dbase + (2 * PLW + r * RSTR) * 4;
                #pragma unroll
                for (int i = 0; i < 4; i++) {
                    CP16(d1 + i * 16, g_wy16_hi + o + i * 4);
                    CP16(d2 + i * 16, g_wy16_lo + o + i * 4);
                }
            }
        }
    };

    // ldmatrix lane offsets (bytes within a buffer)
    const uint32_t a_off = (uint32_t)(warp_m + (lane & 15)) * (RSTR * 4)
                         + ((lane >> 4) * 16);
    const int bg = lane >> 3;
    const uint32_t b_off = (uint32_t)(warp_n + ((bg >> 1) * 8) + (lane & 7)) * (RSTR * 4)
                         + ((bg & 1) * 16);

    auto comp = [&](int buf) {
        const uint32_t bb = smb + (uint32_t)buf * BUFW * 4;
        #pragma unroll
        for (int ks = 0; ks < 2; ks++) {
            const uint32_t kb = ks * 32;
            if (MODE == 0) {
                // A split (planes 0,1), W single (plane 2)
                uint32_t ah[2][4], al[2][4];
                #pragma unroll
                for (int f = 0; f < 2; f++) {
                    LDSM4(ah[f], bb + a_off + f * (16 * RSTR * 4) + kb);
                    LDSM4(al[f], bb + a_off + PLW * 4 + f * (16 * RSTR * 4) + kb);
                }
                #pragma unroll
                for (int p = 0; p < 4; p++) {
                    uint32_t b[4];
                    LDSM4(b, bb + b_off + 2 * PLW * 4 + p * (16 * RSTR * 4) + kb);
                    #pragma unroll
                    for (int jj = 0; jj < 2; jj++) {
                        const int j = 2 * p + jj;
                        #pragma unroll
                        for (int f = 0; f < 2; f++) {
                            MMA_F16(acc[f][j], ah[f], b[2*jj], b[2*jj+1]);
                            MMA_F16(acc[f][j], al[f], b[2*jj], b[2*jj+1]);
                        }
                    }
                }
            } else {
                // A single (plane 0), W split (planes 1,2)
                uint32_t a[2][4];
                #pragma unroll
                for (int f = 0; f < 2; f++)
                    LDSM4(a[f], bb + a_off + f * (16 * RSTR * 4) + kb);
                #pragma unroll
                for (int p = 0; p < 4; p++) {
                    uint32_t bh[4], bl[4];
                    LDSM4(bh, bb + b_off + PLW * 4 + p * (16 * RSTR * 4) + kb);
                    LDSM4(bl, bb + b_off + 2 * PLW * 4 + p * (16 * RSTR * 4) + kb);
                    #pragma unroll
                    for (int jj = 0; jj < 2; jj++) {
                        const int j = 2 * p + jj;
                        #pragma unroll
                        for (int f = 0; f < 2; f++) {
                            MMA_F16(acc[f][j], a[f], bh[2*jj], bh[2*jj+1]);
                            MMA_F16(acc[f][j], a[f], bl[2*jj], bl[2*jj+1]);
                        }
                    }
                }
            }
        }
    };

    cpy(0, 0); CP_COMMIT();
    cpy(1, 1); CP_COMMIT();
    #pragma unroll 1
    for (int c = 0; c < NC; c++) {
        if (c + 1 < NC) asm volatile("cp.async.wait_group 1;" ::: "memory");
        else            asm volatile("cp.async.wait_group 0;" ::: "memory");
        __syncthreads();
        comp(c & 1);
        __syncthreads();
        if (c + 2 < NC) { cpy(c + 2, c & 1); CP_COMMIT(); }
    }

    float* dst;
    int stride;
    if (MODE == 0) { dst = (float*)g_bu + (size_t)ntile * 128; stride = 512; }
    else           { dst = y;                                   stride = HOUT; }
    #pragma unroll
    for (int f = 0; f < 2; f++) {
        const int m = m0 + warp_m + f * 16 + (lane >> 2);
        #pragma unroll
        for (int j = 0; j < 8; j++) {
            const int n = warp_n + j * 8 + (lane & 3) * 2;
            *(float2*)(dst + (size_t)m * stride + n) =
                make_float2(acc[f][j][0], acc[f][j][1]);
            *(float2*)(dst + (size_t)(m + 8) * stride + n) =
                make_float2(acc[f][j][2], acc[f][j][3]);
        }
    }
}

// ============================== scan kernels ===============================
__device__ __forceinline__ void lam_of(const float* __restrict__ nu_log,
                                       const float* __restrict__ th_log,
                                       int n, float& lr, float& li) {
    float mod = expf(-expf(nu_log[n]));
    float th  = expf(th_log[n]);
    lr = mod * cosf(th);
    li = mod * sinf(th);
}

__global__ __launch_bounds__(NST) void scan_phase1(
    const float* __restrict__ nu_log, const float* __restrict__ th_log)
{
    int b = blockIdx.x / (NCH - 1), c = blockIdx.x % (NCH - 1);
    int n = threadIdx.x;
    float lr, li; lam_of(nu_log, th_log, n, lr, li);
    float xr = 0.f, xi = 0.f;
    size_t base = ((size_t)b * SEQ + (size_t)c * CHUNK) * NST + n;
    float2 buf[16];
    #pragma unroll 1
    for (int g = 0; g < CHUNK / 16; g++) {
        #pragma unroll
        for (int i = 0; i < 16; i++)
            buf[i] = g_bu[base + (size_t)(g * 16 + i) * NST];
        #pragma unroll
        for (int i = 0; i < 16; i++) {
            float br = buf[i].x, bi = buf[i].y;
            float nxr = fmaf(lr, xr, fmaf(-li, xi, br));
            float nxi = fmaf(lr, xi, fmaf( li, xr, bi));
            xr = nxr; xi = nxi;
        }
    }
    g_part[(b * NCH + c) * NST + n] = make_float2(xr, xi);
}

__global__ __launch_bounds__(NST) void scan_phase2(
    const float* __restrict__ nu_log, const float* __restrict__ th_log)
{
    int b = blockIdx.x;
    int n = threadIdx.x;
    float lr, li; lam_of(nu_log, th_log, n, lr, li);
    float Lr = lr, Li = li;
    #pragma unroll
    for (int i = 0; i < 6; i++) {
        float nr = Lr * Lr - Li * Li;
        float ni = 2.f * Lr * Li;
        Lr = nr; Li = ni;
    }
    float sr = 0.f, si = 0.f;
    float2 buf[16];
    #pragma unroll 1
    for (int g = 0; g < NCH / 16; g++) {
        #pragma unroll
        for (int i = 0; i < 16; i++)
            buf[i] = g_part[(b * NCH + g * 16 + i) * NST + n];
        #pragma unroll
        for (int i = 0; i < 16; i++) {
            int idx = (b * NCH + g * 16 + i) * NST + n;
            g_part[idx] = make_float2(sr, si);
            float nsr = fmaf(Lr, sr, fmaf(-Li, si, buf[i].x));
            float nsi = fmaf(Lr, si, fmaf( Li, sr, buf[i].y));
            sr = nsr; si = nsi;
        }
    }
}

__global__ __launch_bounds__(NST) void scan_phase3(
    const float* __restrict__ nu_log, const float* __restrict__ th_log)
{
    int b = blockIdx.x / NCH, c = blockIdx.x % NCH;
    int n = threadIdx.x;
    float lr, li; lam_of(nu_log, th_log, n, lr, li);
    float2 s = g_part[(b * NCH + c) * NST + n];
    float xr = s.x, xi = s.y;
    size_t base = ((size_t)b * SEQ + (size_t)c * CHUNK) * NST + n;
    float2 buf[16];
    #pragma unroll 1
    for (int g = 0; g < CHUNK / 16; g++) {
        #pragma unroll
        for (int i = 0; i < 16; i++)
            buf[i] = g_bu[base + (size_t)(g * 16 + i) * NST];
        #pragma unroll
        for (int i = 0; i < 16; i++) {
            size_t off = base + (size_t)(g * 16 + i) * NST;
            g_pre16[off] = packf16(xr, xi);      // pre_t = x_{t-1}, single f16x2
            float br = buf[i].x, bi = buf[i].y;
            float nxr = fmaf(lr, xr, fmaf(-li, xi, br));
            float nxi = fmaf(lr, xi, fmaf( li, xr, bi));
            xr = nxr; xi = nxi;
        }
    }
}

// ================================ launch ===================================
extern "C" void kernel_launch(void* const* d_in, const int* in_sizes, int n_in,
                              void* d_out, int out_size) {
    const float* u         = (const float*)d_in[0];
    const float* nu_log    = (const float*)d_in[1];
    const float* theta_log = (const float*)d_in[2];
    const float* gamma_log = (const float*)d_in[3];
    const float* Bre       = (const float*)d_in[4];
    const float* Bim       = (const float*)d_in[5];
    const float* Cre       = (const float*)d_in[6];
    const float* Cim       = (const float*)d_in[7];
    const float* Dm        = (const float*)d_in[8];
    float* y = (float*)d_out;

    static int attr_done = 0;
    if (!attr_done) {
        cudaFuncSetAttribute(mma_gemm<0>,
                             cudaFuncAttributeMaxDynamicSharedMemorySize, SMEM_BYTES);
        cudaFuncSetAttribute(mma_gemm<1>,
                             cudaFuncAttributeMaxDynamicSharedMemorySize, SMEM_BYTES);
        attr_done = 1;
    }

    prep_all<<<(NU + 512 * 64 + HOUT * 320 + 255) / 256, 256>>>(
        u, Bre, Bim, gamma_log, Cre, Cim, Dm);

    dim3 gb(4, MTOT / 128);
    mma_gemm<0><<<gb, 256, SMEM_BYTES>>>(nullptr);

    scan_phase1<<<BSZ * (NCH - 1), NST>>>(nu_log, theta_log);
    scan_phase2<<<BSZ, NST>>>(nu_log, theta_log);
    scan_phase3<<<BSZ * NCH, NST>>>(nu_log, theta_log);

    dim3 gy(1, MTOT / 128);
    mma_gemm<1><<<gy, 256, SMEM_BYTES>>>(y);
}

// round 10
// speedup vs baseline: 1.8761x; 1.3166x over previous
#include <cuda_runtime.h>
#include <cuda_fp16.h>
#include <math.h>
#include <stdint.h>

#define BSZ   16
#define SEQ   4096
#define NST   256
#define HIN   128
#define HOUT  128
#define MTOT  (BSZ*SEQ)      // 65536
#define CHUNK 64
#define NCH   (SEQ/CHUNK)    // 64

// ------------------------------ scratch -----------------------------------
__device__ float2   g_bu[(size_t)MTOT*NST];     // fp32 Bu (re,im), scan input
__device__ float2   g_part[BSZ*NCH*NST];
__device__ uint32_t g_pre16[(size_t)MTOT*256];  // f16x2 pre-states
__device__ uint32_t g_u16[(size_t)MTOT*64];     // f16x2 u
__device__ uint32_t g_wbu16[512*64];            // f16x2 gamma*B (interleaved re/im rows)
__device__ uint32_t g_wy16[HOUT*320];           // f16x2 [Cre|-Cim interleave, D]

__device__ __forceinline__ uint32_t packf16(float v0, float v1) {
    uint32_t r;
    asm("cvt.rn.f16x2.f32 %0, %1, %2;" : "=r"(r) : "f"(v1), "f"(v0));
    return r;   // v0 in lower half
}

#define MMA_F16(d, a, b0, b1)                                         \
    asm("mma.sync.aligned.m16n8k16.row.col.f32.f16.f16.f32 "          \
        "{%0,%1,%2,%3},{%4,%5,%6,%7},{%8,%9},{%0,%1,%2,%3};"          \
        : "+f"(d[0]), "+f"(d[1]), "+f"(d[2]), "+f"(d[3])              \
        : "r"(a[0]), "r"(a[1]), "r"(a[2]), "r"(a[3]), "r"(b0), "r"(b1))

#define LDSM4(r, addr)                                                \
    asm volatile("ldmatrix.sync.aligned.m8n8.x4.shared.b16 "          \
                 "{%0,%1,%2,%3}, [%4];"                               \
                 : "=r"((r)[0]), "=r"((r)[1]), "=r"((r)[2]), "=r"((r)[3]) \
                 : "r"(addr))

#define CP16(dst, src)                                                \
    asm volatile("cp.async.cg.shared.global [%0], [%1], 16;"          \
                 :: "r"(dst), "l"(src))
#define CP_COMMIT() asm volatile("cp.async.commit_group;" ::: "memory")

// smem: 2 buffers x 2 planes (A, W) x 128 rows x 20 words (80B stride,
// 16B-aligned, ldmatrix-conflict-free).
#define CHW    16
#define RSTR   20
#define PLW    (128*RSTR)       // 2560 words/plane
#define BUFW   (2*PLW)          // 5120
#define SMEM_BYTES (2*BUFW*4)   // 40960 -> 2 CTAs/SM comfortably

// ---------------------------------------------------------------------------
// prep: single kernel converts u + assembles both weight matrices (fp16).
//   [0, NU)          : u
//   [NU, NU+32768)   : wbu
//   [NU+.., +40960)  : wy
// ---------------------------------------------------------------------------
#define NU (MTOT*64)
__global__ __launch_bounds__(256) void prep_all(
    const float* __restrict__ u,
    const float* __restrict__ Bre, const float* __restrict__ Bim,
    const float* __restrict__ gamma_log,
    const float* __restrict__ Cre, const float* __restrict__ Cim,
    const float* __restrict__ Dm)
{
    size_t i = (size_t)blockIdx.x * 256 + threadIdx.x;
    if (i < (size_t)NU) {
        float2 v = ((const float2*)u)[i];
        g_u16[i] = packf16(v.x, v.y);
    } else if (i < (size_t)NU + 512 * 64) {
        int t = (int)(i - NU);
        int n = t >> 6, j = t & 63;
        const float* B = (n & 1) ? Bim : Bre;
        float g = expf(gamma_log[n >> 1]);
        g_wbu16[t] = packf16(B[(n >> 1) * HIN + 2 * j] * g,
                             B[(n >> 1) * HIN + 2 * j + 1] * g);
    } else if (i < (size_t)NU + 512 * 64 + HOUT * 320) {
        int t = (int)(i - NU - 512 * 64);
        int o = t / 320, j = t % 320;
        float v0, v1;
        if (j < 256) { v0 = Cre[o * NST + j]; v1 = -Cim[o * NST + j]; }
        else { v0 = Dm[o * HIN + 2 * (j - 256)]; v1 = Dm[o * HIN + 2 * (j - 256) + 1]; }
        g_wy16[t] = packf16(v0, v1);
    }
}

// ---------------------------------------------------------------------------
// fp16 tensor-core GEMM: C[128m,128n] = A[128,K] x W[128n,K]^T, fp32 accum.
// MODE 0: A=u16 (K=128, 4 chunks); W=wbu16 tile; out -> g_bu fp32 (stride 512)
// MODE 1: A=[pre16|u16] (K=640, 20 chunks); W=wy16; out -> y (stride 128)
// ---------------------------------------------------------------------------
template<int MODE>
__global__ __launch_bounds__(256, 2) void mma_gemm(float* __restrict__ y)
{
    extern __shared__ uint32_t sm[];
    uint32_t smb;
    asm("{ .reg .u64 t; cvta.to.shared.u64 t, %1; cvt.u32.u64 %0, t; }"
        : "=r"(smb) : "l"(sm));
    const int tid = threadIdx.x, lane = tid & 31, wid = tid >> 5;
    const int warp_m = (wid & 3) * 32, warp_n = (wid >> 2) * 64;
    const int ntile = (MODE == 0) ? blockIdx.x : 0;
    const int m0 = blockIdx.y * 128;
    const int NC = (MODE == 0) ? 4 : 20;

    float acc[2][8][4];
    #pragma unroll
    for (int f = 0; f < 2; f++)
        #pragma unroll
        for (int j = 0; j < 8; j++)
            #pragma unroll
            for (int q = 0; q < 4; q++) acc[f][j][q] = 0.f;

    auto cpy = [&](int c, int buf) {
        const uint32_t dbase = smb + (uint32_t)buf * BUFW * 4;
        if (tid < 128) {
            const int r = tid;
            const uint32_t* s;
            if (MODE == 0) {
                s = g_u16 + (size_t)(m0 + r) * 64 + c * CHW;
            } else if (c < 16) {
                s = g_pre16 + (size_t)(m0 + r) * 256 + c * CHW;
            } else {
                s = g_u16 + (size_t)(m0 + r) * 64 + (c - 16) * CHW;
            }
            uint32_t d0 = dbase + (r * RSTR) * 4;
            #pragma unroll
            for (int i = 0; i < 4; i++) CP16(d0 + i * 16, s + i * 4);
        } else {
            const int r = tid - 128;
            const uint32_t* s;
            if (MODE == 0) s = g_wbu16 + (size_t)(ntile * 128 + r) * 64 + c * CHW;
            else           s = g_wy16 + (size_t)r * 320 + c * CHW;
            uint32_t d1 = dbase + (PLW + r * RSTR) * 4;
            #pragma unroll
            for (int i = 0; i < 4; i++) CP16(d1 + i * 16, s + i * 4);
        }
    };

    // ldmatrix lane offsets (bytes within a buffer)
    const uint32_t a_off = (uint32_t)(warp_m + (lane & 15)) * (RSTR * 4)
                         + ((lane >> 4) * 16);
    const int bg = lane >> 3;
    const uint32_t b_off = (uint32_t)(warp_n + ((bg >> 1) * 8) + (lane & 7)) * (RSTR * 4)
                         + ((bg & 1) * 16) + PLW * 4;

    auto comp = [&](int buf) {
        const uint32_t bb = smb + (uint32_t)buf * BUFW * 4;
        #pragma unroll
        for (int ks = 0; ks < 2; ks++) {
            const uint32_t kb = ks * 32;
            uint32_t a[2][4];
            #pragma unroll
            for (int f = 0; f < 2; f++)
                LDSM4(a[f], bb + a_off + f * (16 * RSTR * 4) + kb);
            #pragma unroll
            for (int p = 0; p < 4; p++) {
                uint32_t b[4];
                LDSM4(b, bb + b_off + p * (16 * RSTR * 4) + kb);
                #pragma unroll
                for (int jj = 0; jj < 2; jj++) {
                    const int j = 2 * p + jj;
                    #pragma unroll
                    for (int f = 0; f < 2; f++)
                        MMA_F16(acc[f][j], a[f], b[2*jj], b[2*jj+1]);
                }
            }
        }
    };

    cpy(0, 0); CP_COMMIT();
    cpy(1, 1); CP_COMMIT();
    #pragma unroll 1
    for (int c = 0; c < NC; c++) {
        if (c + 1 < NC) asm volatile("cp.async.wait_group 1;" ::: "memory");
        else            asm volatile("cp.async.wait_group 0;" ::: "memory");
        __syncthreads();
        comp(c & 1);
        __syncthreads();
        if (c + 2 < NC) { cpy(c + 2, c & 1); CP_COMMIT(); }
    }

    float* dst;
    int stride;
    if (MODE == 0) { dst = (float*)g_bu + (size_t)ntile * 128; stride = 512; }
    else           { dst = y;                                   stride = HOUT; }
    #pragma unroll
    for (int f = 0; f < 2; f++) {
        const int m = m0 + warp_m + f * 16 + (lane >> 2);
        #pragma unroll
        for (int j = 0; j < 8; j++) {
            const int n = warp_n + j * 8 + (lane & 3) * 2;
            *(float2*)(dst + (size_t)m * stride + n) =
                make_float2(acc[f][j][0], acc[f][j][1]);
            *(float2*)(dst + (size_t)(m + 8) * stride + n) =
                make_float2(acc[f][j][2], acc[f][j][3]);
        }
    }
}

// ============================== scan kernels ===============================
__device__ __forceinline__ void lam_of(const float* __restrict__ nu_log,
                                       const float* __restrict__ th_log,
                                       int n, float& lr, float& li) {
    float mod = expf(-expf(nu_log[n]));
    float th  = expf(th_log[n]);
    lr = mod * cosf(th);
    li = mod * sinf(th);
}

__global__ __launch_bounds__(NST) void scan_phase1(
    const float* __restrict__ nu_log, const float* __restrict__ th_log)
{
    int b = blockIdx.x / (NCH - 1), c = blockIdx.x % (NCH - 1);
    int n = threadIdx.x;
    float lr, li; lam_of(nu_log, th_log, n, lr, li);
    float xr = 0.f, xi = 0.f;
    size_t base = ((size_t)b * SEQ + (size_t)c * CHUNK) * NST + n;
    float2 buf[16];
    #pragma unroll 1
    for (int g = 0; g < CHUNK / 16; g++) {
        #pragma unroll
        for (int i = 0; i < 16; i++)
            buf[i] = g_bu[base + (size_t)(g * 16 + i) * NST];
        #pragma unroll
        for (int i = 0; i < 16; i++) {
            float br = buf[i].x, bi = buf[i].y;
            float nxr = fmaf(lr, xr, fmaf(-li, xi, br));
            float nxi = fmaf(lr, xi, fmaf( li, xr, bi));
            xr = nxr; xi = nxi;
        }
    }
    g_part[(b * NCH + c) * NST + n] = make_float2(xr, xi);
}

__global__ __launch_bounds__(NST) void scan_phase2(
    const float* __restrict__ nu_log, const float* __restrict__ th_log)
{
    int b = blockIdx.x;
    int n = threadIdx.x;
    float lr, li; lam_of(nu_log, th_log, n, lr, li);
    float Lr = lr, Li = li;
    #pragma unroll
    for (int i = 0; i < 6; i++) {
        float nr = Lr * Lr - Li * Li;
        float ni = 2.f * Lr * Li;
        Lr = nr; Li = ni;
    }
    float sr = 0.f, si = 0.f;
    float2 buf[16];
    #pragma unroll 1
    for (int g = 0; g < NCH / 16; g++) {
        #pragma unroll
        for (int i = 0; i < 16; i++)
            buf[i] = g_part[(b * NCH + g * 16 + i) * NST + n];
        #pragma unroll
        for (int i = 0; i < 16; i++) {
            int idx = (b * NCH + g * 16 + i) * NST + n;
            g_part[idx] = make_float2(sr, si);
            float nsr = fmaf(Lr, sr, fmaf(-Li, si, buf[i].x));
            float nsi = fmaf(Lr, si, fmaf( Li, sr, buf[i].y));
            sr = nsr; si = nsi;
        }
    }
}

__global__ __launch_bounds__(NST) void scan_phase3(
    const float* __restrict__ nu_log, const float* __restrict__ th_log)
{
    int b = blockIdx.x / NCH, c = blockIdx.x % NCH;
    int n = threadIdx.x;
    float lr, li; lam_of(nu_log, th_log, n, lr, li);
    float2 s = g_part[(b * NCH + c) * NST + n];
    float xr = s.x, xi = s.y;
    size_t base = ((size_t)b * SEQ + (size_t)c * CHUNK) * NST + n;
    float2 buf[16];
    #pragma unroll 1
    for (int g = 0; g < CHUNK / 16; g++) {
        #pragma unroll
        for (int i = 0; i < 16; i++)
            buf[i] = g_bu[base + (size_t)(g * 16 + i) * NST];
        #pragma unroll
        for (int i = 0; i < 16; i++) {
            size_t off = base + (size_t)(g * 16 + i) * NST;
            g_pre16[off] = packf16(xr, xi);      // pre_t = x_{t-1}
            float br = buf[i].x, bi = buf[i].y;
            float nxr = fmaf(lr, xr, fmaf(-li, xi, br));
            float nxi = fmaf(lr, xi, fmaf( li, xr, bi));
            xr = nxr; xi = nxi;
        }
    }
}

// ================================ launch ===================================
extern "C" void kernel_launch(void* const* d_in, const int* in_sizes, int n_in,
                              void* d_out, int out_size) {
    const float* u         = (const float*)d_in[0];
    const float* nu_log    = (const float*)d_in[1];
    const float* theta_log = (const float*)d_in[2];
    const float* gamma_log = (const float*)d_in[3];
    const float* Bre       = (const float*)d_in[4];
    const float* Bim       = (const float*)d_in[5];
    const float* Cre       = (const float*)d_in[6];
    const float* Cim       = (const float*)d_in[7];
    const float* Dm        = (const float*)d_in[8];
    float* y = (float*)d_out;

    static int attr_done = 0;
    if (!attr_done) {
        cudaFuncSetAttribute(mma_gemm<0>,
                             cudaFuncAttributeMaxDynamicSharedMemorySize, SMEM_BYTES);
        cudaFuncSetAttribute(mma_gemm<1>,
                             cudaFuncAttributeMaxDynamicSharedMemorySize, SMEM_BYTES);
        attr_done = 1;
    }

    prep_all<<<(NU + 512 * 64 + HOUT * 320 + 255) / 256, 256>>>(
        u, Bre, Bim, gamma_log, Cre, Cim, Dm);

    dim3 gb(4, MTOT / 128);
    mma_gemm<0><<<gb, 256, SMEM_BYTES>>>(nullptr);

    scan_phase1<<<BSZ * (NCH - 1), NST>>>(nu_log, theta_log);
    scan_phase2<<<BSZ, NST>>>(nu_log, theta_log);
    scan_phase3<<<BSZ * NCH, NST>>>(nu_log, theta_log);

    dim3 gy(1, MTOT / 128);
    mma_gemm<1><<<gy, 256, SMEM_BYTES>>>(y);
}